// round 1
// baseline (speedup 1.0000x reference)
#include <cuda_runtime.h>
#include <cstdint>

// state: [2, 4096, 512] float32. Apply 4 CNOT permutations composed into one
// index map. out[n, i, b] = in[n, src(i), b].
//
// PAIRS = [(0,1), (2,3), (5,2), (11,7)], qubit q -> bit (11-q).
// S4[i] = S0[p1(p2(p3(p4(i))))]  => compute src by applying p4,p3,p2,p1 in that order.

static __device__ __forceinline__ unsigned src_index(unsigned j) {
    // p4: (c=11, t=7)  -> cbit at shift 0, flip bit 4
    j ^= ((j >> 0) & 1u) << 4;
    // p3: (c=5, t=2)   -> cbit at shift 6, flip bit 9
    j ^= ((j >> 6) & 1u) << 9;
    // p2: (c=2, t=3)   -> cbit at shift 9, flip bit 8
    j ^= ((j >> 9) & 1u) << 8;
    // p1: (c=0, t=1)   -> cbit at shift 11, flip bit 10
    j ^= ((j >> 11) & 1u) << 10;
    return j;
}

// Each thread moves one float4. Row = 512 floats = 128 float4.
// Total float4s = 2 * 4096 * 128 = 1,048,576.
__global__ __launch_bounds__(256) void cnot_perm_copy(
    const float4* __restrict__ in, float4* __restrict__ out)
{
    unsigned idx = blockIdx.x * blockDim.x + threadIdx.x;   // 0 .. 2^20-1
    unsigned b4  = idx & 127u;          // float4 column within row
    unsigned row = idx >> 7;            // 0 .. 8191
    unsigned i   = row & 4095u;         // basis index within block
    unsigned n   = row >> 12;           // block (0 or 1)

    unsigned src = src_index(i);
    out[idx] = in[((n << 12) | src) * 128u + b4];
}

extern "C" void kernel_launch(void* const* d_in, const int* in_sizes, int n_in,
                              void* d_out, int out_size) {
    const float4* in  = (const float4*)d_in[0];
    float4*       out = (float4*)d_out;
    // 2 * 4096 * 512 floats = 1,048,576 float4s; 256 threads/block -> 4096 blocks
    cnot_perm_copy<<<4096, 256>>>(in, out);
}